// round 3
// baseline (speedup 1.0000x reference)
#include <cuda_runtime.h>
#include <cuda_bf16.h>

// Problem constants (fixed by setup_inputs)
#define BB 64      // batch
#define TT 256     // time steps
#define FF 64      // feature
#define UU 512     // units
#define GG 2048    // 4*U
#define K0 576     // F + U (layer0 concat dim)
#define K1 1024    // U + U (layer1 concat dim)

#define NCTA 128
#define NTHR 256
#define UPC 4       // u-columns owned per CTA (512/128)
#define NCOL 16     // gate-columns per CTA (4 gates * UPC)
#define SK0 580     // padded smem stride for ws0 (multiple of 4 -> float4-aligned)
#define SK1 1028    // padded smem stride for ws1 (multiple of 4)
#define SHS 68      // padded smem stride for h-chunk rows

// Persistent device state (allocation-free scratch)
__device__ float g_h0[2][BB * UU];
__device__ float g_h1[2][BB * UU];
__device__ float g_dech1[BB * TT * UU];   // decoder layer-1 outputs for projection (32MB)
__device__ unsigned int g_barrier = 0;    // monotonic, wrap-safe

__device__ __forceinline__ float sigm(float x) {
    return 1.0f / (1.0f + __expf(-x));
}

// Grid-wide barrier: monotonic counter, generation = multiples of NCTA.
// Wrap-safe signed compare; counter never reset (2^32 divisible by NCTA).
__device__ __forceinline__ void grid_sync() {
    __syncthreads();
    if (threadIdx.x == 0) {
        __threadfence();
        unsigned int me = atomicAdd(&g_barrier, 1u) + 1u;
        unsigned int target = ((me + (NCTA - 1u)) / NCTA) * NCTA;
        while ((int)(*(volatile unsigned int*)&g_barrier - target) < 0) {
            __nanosleep(32);
        }
        __threadfence();
    }
    __syncthreads();
}

#define SMEM_FLOATS (NCOL*SK0 + NCOL*SK1 + 64*SHS + 16*65 + 2*UPC*BB + 32)
#define SMEM_BYTES  (SMEM_FLOATS * 4)

__global__ void __launch_bounds__(NTHR, 1)
lstm_persistent(const float* __restrict__ inputs,
                const float* __restrict__ targets,
                const float* __restrict__ eW0, const float* __restrict__ eb0,
                const float* __restrict__ eW1, const float* __restrict__ eb1,
                const float* __restrict__ dW0, const float* __restrict__ db0,
                const float* __restrict__ dW1, const float* __restrict__ db1)
{
    extern __shared__ float smem[];
    float* ws0   = smem;
    float* ws1   = ws0 + NCOL * SK0;
    float* sh    = ws1 + NCOL * SK1;
    float* gacc  = sh + 64 * SHS;
    float* sc    = gacc + 16 * 65;          // [layer][ul][b]
    float* sbias = sc + 2 * UPC * BB;       // [0..15]=layer0, [16..31]=layer1

    const int tid = threadIdx.x;
    const int cta = blockIdx.x;
    const int u0  = cta * UPC;

    const int c   = tid & 15;       // gate-col within CTA: gate = c>>2, ul = c&3
    const int grp = tid >> 4;       // b-group: b = grp*4 + i

    const int ub  = tid & 63;
    const int uul = tid >> 6;

    {
        int i = cta * NTHR + tid;               // B*U == NCTA*NTHR == 32768
        g_h0[0][i] = 0.0f;
        g_h1[0][i] = 0.0f;
    }
    for (int i = tid; i < 2 * UPC * BB; i += NTHR) sc[i] = 0.0f;
    grid_sync();

    for (int pass = 0; pass < 2; ++pass) {
        const float* W0 = pass ? dW0 : eW0;
        const float* b0 = pass ? db0 : eb0;
        const float* W1 = pass ? dW1 : eW1;
        const float* b1 = pass ? db1 : eb1;
        const float* xs = pass ? targets : inputs;

        {
            int gcol = (c >> 2) * UU + u0 + (c & 3);
            for (int k = tid >> 4; k < K0; k += 16) ws0[c * SK0 + k] = W0[k * GG + gcol];
            for (int k = tid >> 4; k < K1; k += 16) ws1[c * SK1 + k] = W1[k * GG + gcol];
            if (tid < 16) {
                sbias[tid] = b0[(tid >> 2) * UU + u0 + (tid & 3)];
            } else if (tid < 32) {
                int cc = tid - 16;
                sbias[tid] = b1[(cc >> 2) * UU + u0 + (cc & 3)];
            }
        }
        __syncthreads();

        for (int t = 0; t < TT; ++t) {
            const int rp = t & 1, wp = rp ^ 1;
            const float* hr0_old = g_h0[rp];
            const float* hr0_new = g_h0[wp];
            const float* hr1_old = g_h1[rp];
            const float* xbase   = xs + t * FF;

            // ================= LAYER 0 : K = 576 =================
            {
                float acc0 = 0.f, acc1 = 0.f, acc2 = 0.f, acc3 = 0.f;
                for (int ch = 0; ch < 9; ++ch) {
                    #pragma unroll
                    for (int j = 0; j < 4; ++j) {
                        int idx = tid + j * NTHR;
                        int row = idx >> 4;
                        int q   = (idx & 15) << 2;
                        float4 v;
                        if (ch == 0) {
                            v = __ldg((const float4*)(xbase + row * (TT * FF) + q));
                        } else {
                            v = __ldcg((const float4*)(hr0_old + row * UU + (ch - 1) * 64 + q));
                        }
                        *(float4*)(sh + row * SHS + q) = v;
                    }
                    __syncthreads();
                    const float* wrow = ws0 + c * SK0 + ch * 64;
                    #pragma unroll
                    for (int kk = 0; kk < 64; kk += 4) {
                        float4 wv = *(const float4*)(wrow + kk);
                        float4 h0v = *(const float4*)(sh + (grp * 4 + 0) * SHS + kk);
                        float4 h1v = *(const float4*)(sh + (grp * 4 + 1) * SHS + kk);
                        float4 h2v = *(const float4*)(sh + (grp * 4 + 2) * SHS + kk);
                        float4 h3v = *(const float4*)(sh + (grp * 4 + 3) * SHS + kk);
                        acc0 += wv.x*h0v.x; acc0 += wv.y*h0v.y; acc0 += wv.z*h0v.z; acc0 += wv.w*h0v.w;
                        acc1 += wv.x*h1v.x; acc1 += wv.y*h1v.y; acc1 += wv.z*h1v.z; acc1 += wv.w*h1v.w;
                        acc2 += wv.x*h2v.x; acc2 += wv.y*h2v.y; acc2 += wv.z*h2v.z; acc2 += wv.w*h2v.w;
                        acc3 += wv.x*h3v.x; acc3 += wv.y*h3v.y; acc3 += wv.z*h3v.z; acc3 += wv.w*h3v.w;
                    }
                    __syncthreads();
                }
                gacc[c * 65 + grp * 4 + 0] = acc0;
                gacc[c * 65 + grp * 4 + 1] = acc1;
                gacc[c * 65 + grp * 4 + 2] = acc2;
                gacc[c * 65 + grp * 4 + 3] = acc3;
                __syncthreads();
                {
                    float gi = gacc[(0 + uul) * 65 + ub] + sbias[0 + uul];
                    float gj = gacc[(4 + uul) * 65 + ub] + sbias[4 + uul];
                    float gf = gacc[(8 + uul) * 65 + ub] + sbias[8 + uul];
                    float go = gacc[(12 + uul) * 65 + ub] + sbias[12 + uul];
                    float cold = sc[uul * 64 + ub];
                    float cn = sigm(gf + 1.0f) * cold + sigm(gi) * tanhf(gj);
                    sc[uul * 64 + ub] = cn;
                    float h = sigm(go) * tanhf(cn);
                    __stcg(&g_h0[wp][ub * UU + u0 + uul], h);
                }
            }
            grid_sync();

            // ================= LAYER 1 : K = 1024 =================
            {
                float acc0 = 0.f, acc1 = 0.f, acc2 = 0.f, acc3 = 0.f;
                for (int ch = 0; ch < 16; ++ch) {
                    #pragma unroll
                    for (int j = 0; j < 4; ++j) {
                        int idx = tid + j * NTHR;
                        int row = idx >> 4;
                        int q   = (idx & 15) << 2;
                        const float* src = (ch < 8) ? (hr0_new + row * UU + ch * 64)
                                                    : (hr1_old + row * UU + (ch - 8) * 64);
                        float4 v = __ldcg((const float4*)(src + q));
                        *(float4*)(sh + row * SHS + q) = v;
                    }
                    __syncthreads();
                    const float* wrow = ws1 + c * SK1 + ch * 64;
                    #pragma unroll
                    for (int kk = 0; kk < 64; kk += 4) {
                        float4 wv = *(const float4*)(wrow + kk);
                        float4 h0v = *(const float4*)(sh + (grp * 4 + 0) * SHS + kk);
                        float4 h1v = *(const float4*)(sh + (grp * 4 + 1) * SHS + kk);
                        float4 h2v = *(const float4*)(sh + (grp * 4 + 2) * SHS + kk);
                        float4 h3v = *(const float4*)(sh + (grp * 4 + 3) * SHS + kk);
                        acc0 += wv.x*h0v.x; acc0 += wv.y*h0v.y; acc0 += wv.z*h0v.z; acc0 += wv.w*h0v.w;
                        acc1 += wv.x*h1v.x; acc1 += wv.y*h1v.y; acc1 += wv.z*h1v.z; acc1 += wv.w*h1v.w;
                        acc2 += wv.x*h2v.x; acc2 += wv.y*h2v.y; acc2 += wv.z*h2v.z; acc2 += wv.w*h2v.w;
                        acc3 += wv.x*h3v.x; acc3 += wv.y*h3v.y; acc3 += wv.z*h3v.z; acc3 += wv.w*h3v.w;
                    }
                    __syncthreads();
                }
                gacc[c * 65 + grp * 4 + 0] = acc0;
                gacc[c * 65 + grp * 4 + 1] = acc1;
                gacc[c * 65 + grp * 4 + 2] = acc2;
                gacc[c * 65 + grp * 4 + 3] = acc3;
                __syncthreads();
                {
                    float gi = gacc[(0 + uul) * 65 + ub] + sbias[16 + 0 + uul];
                    float gj = gacc[(4 + uul) * 65 + ub] + sbias[16 + 4 + uul];
                    float gf = gacc[(8 + uul) * 65 + ub] + sbias[16 + 8 + uul];
                    float go = gacc[(12 + uul) * 65 + ub] + sbias[16 + 12 + uul];
                    float cold = sc[256 + uul * 64 + ub];
                    float cn = sigm(gf + 1.0f) * cold + sigm(gi) * tanhf(gj);
                    sc[256 + uul * 64 + ub] = cn;
                    float h = sigm(go) * tanhf(cn);
                    __stcg(&g_h1[wp][ub * UU + u0 + uul], h);
                    if (pass == 1) {
                        g_dech1[(ub * TT + t) * UU + u0 + uul] = h;
                    }
                }
            }
            grid_sync();
        }
        __syncthreads();
    }
}

// Final projection + length mask: out[b][t][f] = mask ? h1 @ out_W + out_b : 0
__global__ void proj_kernel(const float* __restrict__ outW,
                            const float* __restrict__ outb,
                            const int* __restrict__ lens,
                            float* __restrict__ out)
{
    __shared__ float shh[UU];
    int bt = blockIdx.x;           // b*T + t
    int b  = bt >> 8;
    int t  = bt & 255;
    int f  = threadIdx.x;          // 0..63

    #pragma unroll
    for (int k = f; k < UU; k += 64) shh[k] = g_dech1[bt * UU + k];
    __syncthreads();

    int len = lens[b];
    float val = 0.0f;
    if (t < len) {
        float acc = outb[f];
        #pragma unroll 8
        for (int k = 0; k < UU; ++k) {
            acc += shh[k] * __ldg(&outW[k * FF + f]);
        }
        val = acc;
    }
    out[bt * FF + f] = val;
}

extern "C" void kernel_launch(void* const* d_in, const int* in_sizes, int n_in,
                              void* d_out, int out_size)
{
    const float* inputs  = (const float*)d_in[0];
    const float* targets = (const float*)d_in[1];
    const int*   lens    = (const int*)d_in[2];
    const float* eW0     = (const float*)d_in[3];
    const float* eb0     = (const float*)d_in[4];
    const float* eW1     = (const float*)d_in[5];
    const float* eb1     = (const float*)d_in[6];
    const float* dW0     = (const float*)d_in[7];
    const float* db0     = (const float*)d_in[8];
    const float* dW1     = (const float*)d_in[9];
    const float* db1     = (const float*)d_in[10];
    const float* outW    = (const float*)d_in[11];
    const float* outb    = (const float*)d_in[12];
    float* out = (float*)d_out;

    cudaFuncSetAttribute(lstm_persistent,
                         cudaFuncAttributeMaxDynamicSharedMemorySize, SMEM_BYTES);

    lstm_persistent<<<NCTA, NTHR, SMEM_BYTES>>>(
        inputs, targets, eW0, eb0, eW1, eb1, dW0, db0, dW1, db1);

    proj_kernel<<<BB * TT, 64>>>(outW, outb, lens, out);
}

// round 4
// speedup vs baseline: 1.6680x; 1.6680x over previous
#include <cuda_runtime.h>
#include <cuda_bf16.h>

// Problem constants (fixed by setup_inputs)
#define BB 64      // batch
#define TT 256     // time steps
#define FF 64      // feature
#define UU 512     // units
#define GG 2048    // 4*U
#define K0 576     // F + U (layer0 concat dim)
#define K1 1024    // U + U (layer1 concat dim)

#define NCTA 128
#define NTHR 256
#define UPC 4       // u-columns owned per CTA
#define NCOL 16     // gate-columns per CTA (4 gates * UPC)
#define SK0 580     // ws0 stride: mult of 4 (f4-aligned), 580 mod 32 = 4 -> conflict-free col spread
#define SK1 1028    // ws1 stride: 1028 mod 32 = 4
#define SHS 68      // sh row stride: 68 mod 32 = 4 -> conflict-free row spread
#define GES 68      // gacc row stride

// Persistent device state (allocation-free scratch)
__device__ float g_h0[2][BB * UU];
__device__ float g_h1[2][BB * UU];
__device__ float g_dech1[BB * TT * UU];   // decoder layer-1 outputs for projection
__device__ unsigned int g_barrier = 0;    // monotonic, wrap-safe

__device__ __forceinline__ float sigm(float x) {
    return 1.0f / (1.0f + __expf(-x));
}

// Grid-wide barrier: monotonic counter; 2^32 divisible by NCTA -> wrap-safe.
__device__ __forceinline__ void grid_sync() {
    __syncthreads();
    if (threadIdx.x == 0) {
        __threadfence();
        unsigned int me = atomicAdd(&g_barrier, 1u) + 1u;
        unsigned int target = ((me + (NCTA - 1u)) / NCTA) * NCTA;
        while ((int)(*(volatile unsigned int*)&g_barrier - target) < 0) {
            __nanosleep(32);
        }
        __threadfence();
    }
    __syncthreads();
}

// SMEM (floats): ws0 9280 + ws1 16448 + 2*sh 8704 + gacc 4352 + sc 512 + sbias 32
#define SMEM_FLOATS (NCOL*SK0 + NCOL*SK1 + 2*64*SHS + 4*NCOL*GES + 2*UPC*BB + 32)
#define SMEM_BYTES  (SMEM_FLOATS * 4)

// 4 FMAs of a float4 dot-product partial
#define DOT4(acc, wv, hv) \
    acc += (wv).x*(hv).x; acc += (wv).y*(hv).y; acc += (wv).z*(hv).z; acc += (wv).w*(hv).w;

__global__ void __launch_bounds__(NTHR, 1)
lstm_persistent(const float* __restrict__ inputs,
                const float* __restrict__ targets,
                const float* __restrict__ eW0, const float* __restrict__ eb0,
                const float* __restrict__ eW1, const float* __restrict__ eb1,
                const float* __restrict__ dW0, const float* __restrict__ db0,
                const float* __restrict__ dW1, const float* __restrict__ db1)
{
    extern __shared__ float smem[];
    float* ws0   = smem;
    float* ws1   = ws0 + NCOL * SK0;
    float* shA   = ws1 + NCOL * SK1;
    float* shB   = shA + 64 * SHS;
    float* gacc  = shB + 64 * SHS;          // [4 ks][16 c][GES rows]
    float* sc    = gacc + 4 * NCOL * GES;   // [layer][ul][b]
    float* sbias = sc + 2 * UPC * BB;       // [0..15]=layer0, [16..31]=layer1

    const int tid = threadIdx.x;
    const int cta = blockIdx.x;
    const int u0  = cta * UPC;

    // compute-phase mapping: 4 cols x 4 rows per thread, split-K=4
    const int cgrp = tid & 3;           // col base (cols cgrp, +4, +8, +12)
    const int rgrp = (tid >> 2) & 15;   // row base (rows rgrp, +16, +32, +48)
    const int ks   = tid >> 6;          // k-slice 0..3 (16 k of each 64-k chunk)

    // staging mapping
    const int prow = tid >> 4;          // 0..15 (rows prow, +16, +32, +48)
    const int pq   = (tid & 15) << 2;   // float4 col offset 0..60

    // update-phase mapping
    const int ub  = tid & 63;
    const int uul = tid >> 6;

    // ---- zero initial states ----
    {
        int i = cta * NTHR + tid;               // B*U == NCTA*NTHR
        g_h0[0][i] = 0.0f;
        g_h1[0][i] = 0.0f;
    }
    for (int i = tid; i < 2 * UPC * BB; i += NTHR) sc[i] = 0.0f;
    grid_sync();

    for (int pass = 0; pass < 2; ++pass) {
        const float* W0 = pass ? dW0 : eW0;
        const float* b0 = pass ? db0 : eb0;
        const float* W1 = pass ? dW1 : eW1;
        const float* b1 = pass ? db1 : eb1;
        const float* xs = pass ? targets : inputs;

        // ---- stage weight slice into SMEM (once per pass) ----
        {
            int cc = tid & 15;
            int gcol = (cc >> 2) * UU + u0 + (cc & 3);
            for (int k = tid >> 4; k < K0; k += 16) ws0[cc * SK0 + k] = W0[k * GG + gcol];
            for (int k = tid >> 4; k < K1; k += 16) ws1[cc * SK1 + k] = W1[k * GG + gcol];
            if (tid < 16) {
                sbias[tid] = b0[(tid >> 2) * UU + u0 + (tid & 3)];
            } else if (tid < 32) {
                int c2 = tid - 16;
                sbias[tid] = b1[(c2 >> 2) * UU + u0 + (c2 & 3)];
            }
        }
        __syncthreads();

        for (int t = 0; t < TT; ++t) {
            const int rp = t & 1, wp = rp ^ 1;
            const float* hr0_old = g_h0[rp];
            const float* hr0_new = g_h0[wp];
            const float* hr1_old = g_h1[rp];
            const float* xbase   = xs + t * FF;

            float4 pre[4];

            // ================= LAYER 0 : 9 chunks (x, h0_old[0..7]) =================
            {
                float a00=0.f,a01=0.f,a02=0.f,a03=0.f;
                float a10=0.f,a11=0.f,a12=0.f,a13=0.f;
                float a20=0.f,a21=0.f,a22=0.f,a23=0.f;
                float a30=0.f,a31=0.f,a32=0.f,a33=0.f;

                // prefetch chunk 0 (x), store to shA, prefetch chunk 1
                #pragma unroll
                for (int j = 0; j < 4; ++j)
                    pre[j] = __ldg((const float4*)(xbase + (prow + 16*j) * (TT*FF) + pq));
                #pragma unroll
                for (int j = 0; j < 4; ++j)
                    *(float4*)(shA + (prow + 16*j) * SHS + pq) = pre[j];
                #pragma unroll
                for (int j = 0; j < 4; ++j)
                    pre[j] = __ldcg((const float4*)(hr0_old + (prow + 16*j) * UU + pq));

                #pragma unroll 1
                for (int ch = 0; ch < 9; ++ch) {
                    __syncthreads();
                    if (ch + 1 < 9) {
                        float* dst = ((ch + 1) & 1) ? shB : shA;
                        #pragma unroll
                        for (int j = 0; j < 4; ++j)
                            *(float4*)(dst + (prow + 16*j) * SHS + pq) = pre[j];
                        if (ch + 2 < 9) {
                            const float* src = hr0_old + (ch + 1) * 64;
                            #pragma unroll
                            for (int j = 0; j < 4; ++j)
                                pre[j] = __ldcg((const float4*)(src + (prow + 16*j) * UU + pq));
                        }
                    }
                    const float* S  = (ch & 1) ? shB : shA;
                    const float* WJ = ws0 + ch * 64;
                    #pragma unroll
                    for (int it = 0; it < 4; ++it) {
                        const int kin = ks * 16 + it * 4;
                        float4 w0 = *(const float4*)(WJ + (cgrp +  0) * SK0 + kin);
                        float4 w1 = *(const float4*)(WJ + (cgrp +  4) * SK0 + kin);
                        float4 w2 = *(const float4*)(WJ + (cgrp +  8) * SK0 + kin);
                        float4 w3 = *(const float4*)(WJ + (cgrp + 12) * SK0 + kin);
                        const float* Sb = S + kin;
                        float4 h0 = *(const float4*)(Sb + (rgrp +  0) * SHS);
                        float4 h1 = *(const float4*)(Sb + (rgrp + 16) * SHS);
                        float4 h2 = *(const float4*)(Sb + (rgrp + 32) * SHS);
                        float4 h3 = *(const float4*)(Sb + (rgrp + 48) * SHS);
                        DOT4(a00,w0,h0) DOT4(a01,w0,h1) DOT4(a02,w0,h2) DOT4(a03,w0,h3)
                        DOT4(a10,w1,h0) DOT4(a11,w1,h1) DOT4(a12,w1,h2) DOT4(a13,w1,h3)
                        DOT4(a20,w2,h0) DOT4(a21,w2,h1) DOT4(a22,w2,h2) DOT4(a23,w2,h3)
                        DOT4(a30,w3,h0) DOT4(a31,w3,h1) DOT4(a32,w3,h2) DOT4(a33,w3,h3)
                    }
                }
                // split-K partials
                {
                    float* gp = gacc + ks * (NCOL * GES) + cgrp * GES + rgrp;
                    gp[0*4*GES +  0] = a00; gp[0*4*GES + 16] = a01; gp[0*4*GES + 32] = a02; gp[0*4*GES + 48] = a03;
                    gp[1*4*GES +  0] = a10; gp[1*4*GES + 16] = a11; gp[1*4*GES + 32] = a12; gp[1*4*GES + 48] = a13;
                    gp[2*4*GES +  0] = a20; gp[2*4*GES + 16] = a21; gp[2*4*GES + 32] = a22; gp[2*4*GES + 48] = a23;
                    gp[3*4*GES +  0] = a30; gp[3*4*GES + 16] = a31; gp[3*4*GES + 32] = a32; gp[3*4*GES + 48] = a33;
                }
                __syncthreads();
                // reduce + cell update
                {
                    float gs[4];
                    #pragma unroll
                    for (int g = 0; g < 4; ++g) {
                        int c = g * 4 + uul;
                        const float* gp = gacc + c * GES + ub;
                        gs[g] = gp[0] + gp[NCOL*GES] + gp[2*NCOL*GES] + gp[3*NCOL*GES] + sbias[c];
                    }
                    float cold = sc[uul * 64 + ub];
                    float cn = sigm(gs[2] + 1.0f) * cold + sigm(gs[0]) * tanhf(gs[1]);
                    sc[uul * 64 + ub] = cn;
                    float h = sigm(gs[3]) * tanhf(cn);
                    __stcg(&g_h0[wp][ub * UU + u0 + uul], h);
                }
            }
            grid_sync();

            // ================= LAYER 1 : 16 chunks (h0_new[0..7], h1_old[0..7]) =================
            {
                float a00=0.f,a01=0.f,a02=0.f,a03=0.f;
                float a10=0.f,a11=0.f,a12=0.f,a13=0.f;
                float a20=0.f,a21=0.f,a22=0.f,a23=0.f;
                float a30=0.f,a31=0.f,a32=0.f,a33=0.f;

                #pragma unroll
                for (int j = 0; j < 4; ++j)
                    pre[j] = __ldcg((const float4*)(hr0_new + (prow + 16*j) * UU + pq));
                #pragma unroll
                for (int j = 0; j < 4; ++j)
                    *(float4*)(shA + (prow + 16*j) * SHS + pq) = pre[j];
                #pragma unroll
                for (int j = 0; j < 4; ++j)
                    pre[j] = __ldcg((const float4*)(hr0_new + (prow + 16*j) * UU + 64 + pq));

                #pragma unroll 1
                for (int ch = 0; ch < 16; ++ch) {
                    __syncthreads();
                    if (ch + 1 < 16) {
                        float* dst = ((ch + 1) & 1) ? shB : shA;
                        #pragma unroll
                        for (int j = 0; j < 4; ++j)
                            *(float4*)(dst + (prow + 16*j) * SHS + pq) = pre[j];
                        if (ch + 2 < 16) {
                            const int chn = ch + 2;
                            const float* src = (chn < 8) ? (hr0_new + chn * 64)
                                                         : (hr1_old + (chn - 8) * 64);
                            #pragma unroll
                            for (int j = 0; j < 4; ++j)
                                pre[j] = __ldcg((const float4*)(src + (prow + 16*j) * UU + pq));
                        }
                    }
                    const float* S  = (ch & 1) ? shB : shA;
                    const float* WJ = ws1 + ch * 64;
                    #pragma unroll
                    for (int it = 0; it < 4; ++it) {
                        const int kin = ks * 16 + it * 4;
                        float4 w0 = *(const float4*)(WJ + (cgrp +  0) * SK1 + kin);
                        float4 w1 = *(const float4*)(WJ + (cgrp +  4) * SK1 + kin);
                        float4 w2 = *(const float4*)(WJ + (cgrp +  8) * SK1 + kin);
                        float4 w3 = *(const float4*)(WJ + (cgrp + 12) * SK1 + kin);
                        const float* Sb = S + kin;
                        float4 h0 = *(const float4*)(Sb + (rgrp +  0) * SHS);
                        float4 h1 = *(const float4*)(Sb + (rgrp + 16) * SHS);
                        float4 h2 = *(const float4*)(Sb + (rgrp + 32) * SHS);
                        float4 h3 = *(const float4*)(Sb + (rgrp + 48) * SHS);
                        DOT4(a00,w0,h0) DOT4(a01,w0,h1) DOT4(a02,w0,h2) DOT4(a03,w0,h3)
                        DOT4(a10,w1,h0) DOT4(a11,w1,h1) DOT4(a12,w1,h2) DOT4(a13,w1,h3)
                        DOT4(a20,w2,h0) DOT4(a21,w2,h1) DOT4(a22,w2,h2) DOT4(a23,w2,h3)
                        DOT4(a30,w3,h0) DOT4(a31,w3,h1) DOT4(a32,w3,h2) DOT4(a33,w3,h3)
                    }
                }
                {
                    float* gp = gacc + ks * (NCOL * GES) + cgrp * GES + rgrp;
                    gp[0*4*GES +  0] = a00; gp[0*4*GES + 16] = a01; gp[0*4*GES + 32] = a02; gp[0*4*GES + 48] = a03;
                    gp[1*4*GES +  0] = a10; gp[1*4*GES + 16] = a11; gp[1*4*GES + 32] = a12; gp[1*4*GES + 48] = a13;
                    gp[2*4*GES +  0] = a20; gp[2*4*GES + 16] = a21; gp[2*4*GES + 32] = a22; gp[2*4*GES + 48] = a23;
                    gp[3*4*GES +  0] = a30; gp[3*4*GES + 16] = a31; gp[3*4*GES + 32] = a32; gp[3*4*GES + 48] = a33;
                }
                __syncthreads();
                {
                    float gs[4];
                    #pragma unroll
                    for (int g = 0; g < 4; ++g) {
                        int c = g * 4 + uul;
                        const float* gp = gacc + c * GES + ub;
                        gs[g] = gp[0] + gp[NCOL*GES] + gp[2*NCOL*GES] + gp[3*NCOL*GES] + sbias[16 + c];
                    }
                    float cold = sc[256 + uul * 64 + ub];
                    float cn = sigm(gs[2] + 1.0f) * cold + sigm(gs[0]) * tanhf(gs[1]);
                    sc[256 + uul * 64 + ub] = cn;
                    float h = sigm(gs[3]) * tanhf(cn);
                    __stcg(&g_h1[wp][ub * UU + u0 + uul], h);
                    if (pass == 1) {
                        g_dech1[(ub * TT + t) * UU + u0 + uul] = h;
                    }
                }
            }
            grid_sync();
        }
        __syncthreads();
    }
}

// Final projection + length mask: out[b][t][f] = mask ? h1 @ out_W + out_b : 0
__global__ void proj_kernel(const float* __restrict__ outW,
                            const float* __restrict__ outb,
                            const int* __restrict__ lens,
                            float* __restrict__ out)
{
    __shared__ float shh[UU];
    int bt = blockIdx.x;           // b*T + t
    int b  = bt >> 8;
    int t  = bt & 255;
    int f  = threadIdx.x;          // 0..63

    #pragma unroll
    for (int k = f; k < UU; k += 64) shh[k] = g_dech1[bt * UU + k];
    __syncthreads();

    int len = lens[b];
    float val = 0.0f;
    if (t < len) {
        float acc = outb[f];
        #pragma unroll 8
        for (int k = 0; k < UU; ++k) {
            acc += shh[k] * __ldg(&outW[k * FF + f]);
        }
        val = acc;
    }
    out[bt * FF + f] = val;
}

extern "C" void kernel_launch(void* const* d_in, const int* in_sizes, int n_in,
                              void* d_out, int out_size)
{
    const float* inputs  = (const float*)d_in[0];
    const float* targets = (const float*)d_in[1];
    const int*   lens    = (const int*)d_in[2];
    const float* eW0     = (const float*)d_in[3];
    const float* eb0     = (const float*)d_in[4];
    const float* eW1     = (const float*)d_in[5];
    const float* eb1     = (const float*)d_in[6];
    const float* dW0     = (const float*)d_in[7];
    const float* db0     = (const float*)d_in[8];
    const float* dW1     = (const float*)d_in[9];
    const float* db1     = (const float*)d_in[10];
    const float* outW    = (const float*)d_in[11];
    const float* outb    = (const float*)d_in[12];
    float* out = (float*)d_out;

    cudaFuncSetAttribute(lstm_persistent,
                         cudaFuncAttributeMaxDynamicSharedMemorySize, SMEM_BYTES);

    lstm_persistent<<<NCTA, NTHR, SMEM_BYTES>>>(
        inputs, targets, eW0, eb0, eW1, eb1, dW0, db0, dW1, db1);

    proj_kernel<<<BB * TT, 64>>>(outW, outb, lens, out);
}